// round 15
// baseline (speedup 1.0000x reference)
#include <cuda_runtime.h>
#include <cstdint>

#define DINLINE __device__ __forceinline__

namespace {
constexpr int L = 160, H = 128, HP = 129, R = 4, BATCH = 2, D = 768;
constexpr int NKJ = H * HP;                              // 16512
constexpr long long WTRI_R = (long long)HP * NKJ;        // 2130048

constexpr long long V_SZ  = (long long)BATCH * R * L * L * HP;  // 26,419,200
constexpr long long LG_SZ = (long long)BATCH * R * L * L * L;   // 32,768,000
constexpr long long OFF_V  = 0;        // W2
constexpr long long OFF_LG = V_SZ;     // alpha
constexpr long long ARENA_SZ = V_SZ + LG_SZ;
constexpr long long W2_B = (long long)R * L * H * L;     // per-b W2 floats
constexpr long long LG_B = (long long)R * L * L * L;     // per-b alpha floats

constexpr int SM_160_128 = (2 * 32 * 164 + 2 * 32 * 128) * 4;  // 74752
constexpr int SM_128_160 = (2 * 32 * 132 + 2 * 32 * 160) * 4;  // 74752
// <80,160> with softmax red buffer [80][20] appended
constexpr int SM_80_160S = (2 * 32 * 84 + 2 * 32 * 160 + 80 * 20) * 4;  // 68864
}

// ------------------------- static device scratch ----------------------------
__device__ float g_hidden[BATCH * L * 4 * H];    // [b*L+l][512]
__device__ float g_scoring[BATCH * L * 2 * H];   // [b*L+l][256]
__device__ float g_inPT[BATCH * HP * L];         // [b][j][z], row j=128 -> 1
__device__ float g_xtailPT[BATCH * HP * L];      // [b][m][y], row m=128 -> 1
__device__ float g_U[(long long)BATCH * R * L * NKJ];   // [(b*R+r)*L+y][k*129+j]
__device__ float g_G[(long long)BATCH * L * NKJ];       // [b][x][q*129+m]
__device__ float g_Gt2[(long long)BATCH * L * H * L];   // [b][x*128+q][y]
__device__ float g_Gt3[(long long)BATCH * L * L * H];   // [b][y][x*128+q]
__device__ float g_HRW[BATCH * L * H];                  // [b][z][q]
__device__ float g_arena[ARENA_SZ];

DINLINE float leaky(float v) { return v >= 0.f ? v : 0.1f * v; }

// ---- cp.async helpers ------------------------------------------------------
DINLINE void cp4(uint32_t dst, const float* src) {
  asm volatile("cp.async.ca.shared.global [%0], [%1], 4;"
               :: "r"(dst), "l"(src));
}
DINLINE void cp16(uint32_t dst, const float* src) {
  asm volatile("cp.async.cg.shared.global [%0], [%1], 16;"
               :: "r"(dst), "l"(src));
}
#define CP_COMMIT() asm volatile("cp.async.commit_group;" ::: "memory")
#define CP_WAIT0()  asm volatile("cp.async.wait_group 0;" ::: "memory")

// ---- cp.async double-buffered GEMM, BK=32, 8x8 microtile, exact tiles -------
// Batched over blockIdx.z: bz = z / ZD, rz = z % ZD.
//   A += bz*sA + rz*sA2;  B += bz*sB + rz*sB2;  C += z*sC.
// REQUIRES: M % BM == 0, N % BN == 0, K % 32 == 0.
// ep: 0 none | 1 leaky(acc+bias[n]) | 2 acc+B[K][n] | 3 acc+A[m][K]
//     4 fused SP+score (BN==128; aux=Gt3; C=out base; see R12)
//     5 softmax over the full row before store (REQUIRES grid.x==1 so
//       BN==N; extra smem red[BM][BN/8] appended after Bs)
template <int BM, int BN, int OCC>
__global__ void __launch_bounds__((BM / 8) * (BN / 8), OCC) gemm6(
    const float* __restrict__ A, const float* __restrict__ B,
    float* __restrict__ C, int M, int N, int K, int lda, int ldb, int ldc,
    long long sA, long long sA2, long long sB, long long sB2, long long sC,
    int ZD, int ep, const float* __restrict__ bias,
    const float* __restrict__ aux) {
  constexpr int NT = (BM / 8) * (BN / 8);
  constexpr int AST = BM + 4;
  constexpr int AR = (BM * 32 + NT - 1) / NT;
  constexpr int BR = (BN * 8 + NT - 1) / NT;
  extern __shared__ float smem[];
  float* As = smem;                 // [2][32][AST]
  float* Bs = smem + 2 * 32 * AST;  // [2][32][BN]
  const int z = blockIdx.z;
  const int bz = z / ZD, rz = z % ZD;
  A += bz * sA + rz * sA2;
  B += bz * sB + rz * sB2;
  C += (long long)z * sC;
  const int tid = threadIdx.x;
  const int tx = tid % (BN / 8), ty = tid / (BN / 8);
  const int m0 = blockIdx.y * BM, n0 = blockIdx.x * BN;

  const uint32_t sbA = (uint32_t)__cvta_generic_to_shared(As);
  const uint32_t sbB = (uint32_t)__cvta_generic_to_shared(Bs);

  auto prefetch = [&](int k0, int s) {
#pragma unroll
    for (int t = 0; t < AR; ++t) {
      int idx = tid + t * NT;
      if (idx < BM * 32) {
        int m = idx >> 5, k = idx & 31;
        cp4(sbA + (((s * 32 + k) * AST + m) << 2),
            A + (long long)(m0 + m) * lda + k0 + k);
      }
    }
#pragma unroll
    for (int t = 0; t < BR; ++t) {
      int idx = tid + t * NT;
      if (idx < BN * 8) {
        int k = idx / (BN / 4), n4 = idx % (BN / 4);
        cp16(sbB + (((s * 32 + k) * BN + n4 * 4) << 2),
             B + (long long)(k0 + k) * ldb + n0 + n4 * 4);
      }
    }
  };

  float acc[8][8] = {};
  prefetch(0, 0);
  CP_COMMIT();
  int buf = 0;
  for (int k0 = 0; k0 < K; k0 += 32) {
    CP_WAIT0();
    __syncthreads();
    const bool next = (k0 + 32) < K;
    if (next) {
      prefetch(k0 + 32, buf ^ 1);
      CP_COMMIT();
    }
    const float* Ab = As + buf * 32 * AST;
    const float* Bb = Bs + buf * 32 * BN;
#pragma unroll 16
    for (int k = 0; k < 32; ++k) {
      float4 A0 = *(const float4*)(Ab + k * AST + ty * 4);
      float4 A1 = *(const float4*)(Ab + k * AST + BM / 2 + ty * 4);
      float4 B0 = *(const float4*)(Bb + k * BN + tx * 4);
      float4 B1 = *(const float4*)(Bb + k * BN + BN / 2 + tx * 4);
      float av[8] = {A0.x, A0.y, A0.z, A0.w, A1.x, A1.y, A1.z, A1.w};
      float bv[8] = {B0.x, B0.y, B0.z, B0.w, B1.x, B1.y, B1.z, B1.w};
#pragma unroll
      for (int i = 0; i < 8; ++i)
#pragma unroll
        for (int j = 0; j < 8; ++j)
          acc[i][j] = fmaf(av[i], bv[j], acc[i][j]);
    }
    buf ^= 1;
  }
  // ---------------- epilogues (tile-exact; no M/N guards) ----------------
  if (ep == 4) {  // fused SP + score; BN==128, n0==0, m0==0
    const int r = rz / L, y = rz % L;
    float4 bb0 = *(const float4*)(bias + tx * 4);
    float4 bb1 = *(const float4*)(bias + BN / 2 + tx * 4);
    const float* gbase = aux + ((long long)(bz * L + y) * L) * H;
#pragma unroll
    for (int i = 0; i < 8; ++i) {
      int m = (i < 4 ? ty * 4 + i : BM / 2 + ty * 4 + (i - 4));
      float4 g0 = *(const float4*)(gbase + (long long)m * H + tx * 4);
      float4 g1 = *(const float4*)(gbase + (long long)m * H + BN / 2 + tx * 4);
      float s = leaky(acc[i][0] + bb0.x) * g0.x + leaky(acc[i][1] + bb0.y) * g0.y +
                leaky(acc[i][2] + bb0.z) * g0.z + leaky(acc[i][3] + bb0.w) * g0.w +
                leaky(acc[i][4] + bb1.x) * g1.x + leaky(acc[i][5] + bb1.y) * g1.y +
                leaky(acc[i][6] + bb1.z) * g1.z + leaky(acc[i][7] + bb1.w) * g1.w;
#pragma unroll
      for (int o = 8; o; o >>= 1) s += __shfl_xor_sync(0xffffffffu, s, o);
      if (tx == 0)
        C[((long long)((bz * R + r) * L + m)) * L + y] = s;
    }
    return;
  }
  if (ep == 5) {  // in-epilogue softmax over the full row (grid.x==1, BN==N)
    constexpr int NC = BN / 8;  // tx count per row
    float* red = smem + 2 * 32 * AST + 2 * 32 * BN;  // [BM][NC]
    int mloc[8];
#pragma unroll
    for (int i = 0; i < 8; ++i)
      mloc[i] = (i < 4 ? ty * 4 + i : BM / 2 + ty * 4 + (i - 4));
    __syncthreads();  // main-loop smem reads done before red overwrites? (red
                      // is a separate region, but keep warps aligned)
#pragma unroll
    for (int i = 0; i < 8; ++i) {
      float lm = acc[i][0];
#pragma unroll
      for (int j = 1; j < 8; ++j) lm = fmaxf(lm, acc[i][j]);
      red[mloc[i] * NC + tx] = lm;
    }
    __syncthreads();
    float mx[8];
#pragma unroll
    for (int i = 0; i < 8; ++i) {
      float m_ = red[mloc[i] * NC];
#pragma unroll
      for (int j = 1; j < NC; ++j) m_ = fmaxf(m_, red[mloc[i] * NC + j]);
      mx[i] = m_;
    }
    __syncthreads();
#pragma unroll
    for (int i = 0; i < 8; ++i) {
      float ls = 0.f;
#pragma unroll
      for (int j = 0; j < 8; ++j) {
        acc[i][j] = __expf(acc[i][j] - mx[i]);
        ls += acc[i][j];
      }
      red[mloc[i] * NC + tx] = ls;
    }
    __syncthreads();
#pragma unroll
    for (int i = 0; i < 8; ++i) {
      float s_ = 0.f;
#pragma unroll
      for (int j = 0; j < NC; ++j) s_ += red[mloc[i] * NC + j];
      float inv = 1.f / s_;
#pragma unroll
      for (int j = 0; j < 8; ++j) acc[i][j] *= inv;
    }
    // fall through to the plain store below (ep treated as none)
#pragma unroll
    for (int i = 0; i < 8; ++i) {
      int m = m0 + mloc[i];
#pragma unroll
      for (int jh = 0; jh < 2; ++jh) {
        int n = (jh ? BN / 2 : 0) + tx * 4;
        float4 v = make_float4(acc[i][jh * 4 + 0], acc[i][jh * 4 + 1],
                               acc[i][jh * 4 + 2], acc[i][jh * 4 + 3]);
        *(float4*)(C + (long long)m * ldc + n) = v;
      }
    }
    return;
  }
  float4 br0 = make_float4(0.f, 0.f, 0.f, 0.f), br1 = br0;
  if (ep == 2) {
    const float* Brow = B + (long long)K * ldb;
    br0 = *(const float4*)(Brow + n0 + tx * 4);
    br1 = *(const float4*)(Brow + n0 + BN / 2 + tx * 4);
  }
#pragma unroll
  for (int i = 0; i < 8; ++i) {
    int m = m0 + (i < 4 ? ty * 4 + i : BM / 2 + ty * 4 + (i - 4));
    float ra = (ep == 3) ? A[(long long)m * lda + K] : 0.f;
#pragma unroll
    for (int jh = 0; jh < 2; ++jh) {
      int n = n0 + (jh ? BN / 2 : 0) + tx * 4;
      float4 v = make_float4(acc[i][jh * 4 + 0], acc[i][jh * 4 + 1],
                             acc[i][jh * 4 + 2], acc[i][jh * 4 + 3]);
      if (ep == 1) {
        v.x = leaky(v.x + bias[n + 0]);
        v.y = leaky(v.y + bias[n + 1]);
        v.z = leaky(v.z + bias[n + 2]);
        v.w = leaky(v.w + bias[n + 3]);
      } else if (ep == 2) {
        float4 br = jh ? br1 : br0;
        v.x += br.x; v.y += br.y; v.z += br.z; v.w += br.w;
      } else if (ep == 3) {
        v.x += ra; v.y += ra; v.z += ra; v.w += ra;
      }
      *(float4*)(C + (long long)m * ldc + n) = v;
    }
  }
}

// ---------------- prep: inPT / xtailPT transposes ---------------------------
__global__ void k_prep2() {
  int t = blockIdx.x * blockDim.x + threadIdx.x;
  const int NPAD = BATCH * HP * L;  // 41280
  if (t < NPAD) {
    int b = t / (HP * L), rem = t % (HP * L);
    int j = rem / L, zz = rem % L;
    g_inPT[t] = (j < H)
        ? g_hidden[(long long)(b * L + zz) * (4 * H) + 3 * H + j] : 1.f;
    return;
  }
  t -= NPAD;
  if (t < NPAD) {
    int b = t / (HP * L), rem = t % (HP * L);
    int m = rem / L, y = rem % L;
    g_xtailPT[t] = (m < H)
        ? g_scoring[(long long)(b * L + y) * (2 * H) + H + m] : 1.f;
  }
}

// ---------------- Gt2[b][xq][y] -> Gt3[b][y][xq] (tiled transpose) ----------
__global__ void k_transpose(const float* __restrict__ in,
                            float* __restrict__ outp) {
  __shared__ float t[32][33];
  int b = blockIdx.z;
  int xq0 = blockIdx.x * 32, y0 = blockIdx.y * 32;
  const float* ip = in + (long long)b * (L * H) * L;
  float* op = outp + (long long)b * L * (L * H);
  int tx = threadIdx.x, ty0 = threadIdx.y;  // 32 x 8
  for (int i = ty0; i < 32; i += 8)
    t[i][tx] = ip[(long long)(xq0 + i) * L + (y0 + tx)];
  __syncthreads();
  for (int i = ty0; i < 32; i += 8)
    op[(long long)(y0 + i) * (L * H) + (xq0 + tx)] = t[tx][i];
}

// ------------------------------- launch --------------------------------------
static const float* pick_by_size(void* const* d_in, const int* in_sizes,
                                 int n_in, int want, int fallback_idx) {
  for (int i = 0; i < n_in; ++i)
    if (in_sizes[i] == want) return (const float*)d_in[i];
  return (const float*)d_in[fallback_idx];
}

extern "C" void kernel_launch(void* const* d_in, const int* in_sizes, int n_in,
                              void* d_out, int out_size) {
  (void)out_size;
  const float* x      = pick_by_size(d_in, in_sizes, n_in, BATCH * L * D, 0);
  const float* Wspan  = pick_by_size(d_in, in_sizes, n_in, D * 4 * H, 1);
  const float* bspan  = pick_by_size(d_in, in_sizes, n_in, 4 * H, 2);
  const float* Wscore = pick_by_size(d_in, in_sizes, n_in, D * 2 * H, 3);
  const float* bscore = pick_by_size(d_in, in_sizes, n_in, 2 * H, 4);
  const float* Wtri   = pick_by_size(d_in, in_sizes, n_in, R * HP * H * HP, 5);
  const float* Wmlp   = pick_by_size(d_in, in_sizes, n_in, H * H, 6);
  const float* bmlp   = pick_by_size(d_in, in_sizes, n_in, H, 7);
  const float* Wfin   = pick_by_size(d_in, in_sizes, n_in, HP * H * HP, 8);
  float* out = (float*)d_out;

  float* d_hidden;  cudaGetSymbolAddress((void**)&d_hidden, g_hidden);
  float* d_scoring; cudaGetSymbolAddress((void**)&d_scoring, g_scoring);
  float* d_inPT;    cudaGetSymbolAddress((void**)&d_inPT, g_inPT);
  float* d_xtailPT; cudaGetSymbolAddress((void**)&d_xtailPT, g_xtailPT);
  float* d_U;       cudaGetSymbolAddress((void**)&d_U, g_U);
  float* d_G;       cudaGetSymbolAddress((void**)&d_G, g_G);
  float* d_Gt2;     cudaGetSymbolAddress((void**)&d_Gt2, g_Gt2);
  float* d_Gt3;     cudaGetSymbolAddress((void**)&d_Gt3, g_Gt3);
  float* d_HRW;     cudaGetSymbolAddress((void**)&d_HRW, g_HRW);
  float* d_arena;   cudaGetSymbolAddress((void**)&d_arena, g_arena);
  float* d_W2 = d_arena + OFF_V;   // [b][(r,y)][k][z]
  float* d_LG = d_arena + OFF_LG;  // alpha [b][(r,y)][x][z]

  cudaFuncSetAttribute(gemm6<160, 128, 2>,
                       cudaFuncAttributeMaxDynamicSharedMemorySize, SM_160_128);
  cudaFuncSetAttribute(gemm6<128, 160, 2>,
                       cudaFuncAttributeMaxDynamicSharedMemorySize, SM_128_160);
  cudaFuncSetAttribute(gemm6<80, 160, 3>,
                       cudaFuncAttributeMaxDynamicSharedMemorySize, SM_80_160S);

  // 1) hidden = leaky(x @ Wspan + bspan)   [320,512], K=768
  gemm6<160, 128, 2><<<dim3(4, 2, 1), 320, SM_160_128>>>(
      x, Wspan, d_hidden, 320, 512, 768, 768, 512, 512,
      0, 0, 0, 0, 0, 1, 1, bspan, nullptr);
  // 2) scoring = leaky(x @ Wscore + bscore) [320,256], K=768
  gemm6<160, 128, 2><<<dim3(2, 2, 1), 320, SM_160_128>>>(
      x, Wscore, d_scoring, 320, 256, 768, 768, 256, 256,
      0, 0, 0, 0, 0, 1, 1, bscore, nullptr);
  // 3) transposes for inPT / xtailPT
  k_prep2<<<(2 * BATCH * HP * L + 255) / 256, 256>>>();
  // 4) U[(b,r)] = h_tail[b] @ Wtri[r][0:128] + Wtri[r][128]; z=(b,r), ZD=R
  gemm6<160, 128, 2><<<dim3(129, 1, BATCH * R), 320, SM_160_128>>>(
      d_hidden + 2 * H, Wtri, d_U, L, NKJ, H, 4 * H, NKJ, NKJ,
      (long long)L * (4 * H), 0, 0, WTRI_R, (long long)L * NKJ,
      R, 2, nullptr, nullptr);
  // 5) G[b] = x_head[b] @ Wfin[0:128] + Wfin[128]; z=b
  gemm6<160, 128, 2><<<dim3(129, 1, BATCH), 320, SM_160_128>>>(
      d_scoring, Wfin, d_G, L, NKJ, H, 2 * H, NKJ, NKJ,
      (long long)L * (2 * H), 0, 0, 0, (long long)L * NKJ,
      1, 2, nullptr, nullptr);
  // 6) Gt2[b] = G[b][:, 0:128] @ xtailPT[b][0:128] + G[..][128]; z=b
  gemm6<128, 160, 2><<<dim3(1, 160, BATCH), 320, SM_128_160>>>(
      d_G, d_xtailPT, d_Gt2, L * H, L, H, HP, L, L,
      (long long)L * NKJ, 0, (long long)HP * L, 0, (long long)(L * H) * L,
      1, 3, nullptr, nullptr);
  // 6b) Gt3[b][y][xq] = transpose(Gt2)
  k_transpose<<<dim3(640, 5, 2), dim3(32, 8)>>>(d_Gt2, d_Gt3);
  // 7) W2[z] = U[z][:, 0:128] @ inPT[b][0:128] + U[z][:, 128]; z=(b,(r,y))
  gemm6<128, 160, 2><<<dim3(1, 1, BATCH * R * L), 320, SM_128_160>>>(
      d_U, d_inPT, d_W2, H, L, H, HP, L, L,
      (long long)R * L * NKJ, NKJ, (long long)HP * L, 0, (long long)H * L,
      R * L, 3, nullptr, nullptr);
  // 8+9) alpha[z] = softmax(h_head[b] @ W2[z]) — softmax fused in epilogue
  gemm6<80, 160, 3><<<dim3(1, 2, BATCH * R * L), 200, SM_80_160S>>>(
      d_hidden + H, d_W2, d_LG, L, L, H, 4 * H, L, L,
      (long long)L * (4 * H), 0, W2_B, (long long)H * L, (long long)L * L,
      R * L, 5, nullptr, nullptr);
  // 10) HRW[b] = h_in_repr[b] [160,128] @ Wmlp [128,128]; z=b
  gemm6<160, 128, 2><<<dim3(1, 1, BATCH), 320, SM_160_128>>>(
      d_hidden, Wmlp, d_HRW, L, H, H, 4 * H, H, H,
      (long long)L * (4 * H), 0, 0, 0, (long long)L * H,
      1, 0, nullptr, nullptr);
  // 11) fused: SP = leaky(alpha @ HRW + bmlp); out = sum_q SP*Gt3 (ep=4)
  gemm6<160, 128, 2><<<dim3(1, 1, BATCH * R * L), 320, SM_160_128>>>(
      d_LG, d_HRW, out, L, H, L, L, H, 0,
      LG_B, (long long)L * L, (long long)L * H, 0, 0,
      R * L, 4, bmlp, d_Gt3);
}

// round 16
// speedup vs baseline: 1.0977x; 1.0977x over previous
#include <cuda_runtime.h>
#include <cstdint>

#define DINLINE __device__ __forceinline__

typedef unsigned long long u64;

namespace {
constexpr int L = 160, H = 128, HP = 129, R = 4, BATCH = 2, D = 768;
constexpr int NKJ = H * HP;                              // 16512
constexpr long long WTRI_R = (long long)HP * NKJ;        // 2130048

constexpr long long V_SZ  = (long long)BATCH * R * L * L * HP;  // 26,419,200
constexpr long long LG_SZ = (long long)BATCH * R * L * L * L;   // 32,768,000
constexpr long long OFF_V  = 0;        // W2
constexpr long long OFF_LG = V_SZ;     // alpha
constexpr long long ARENA_SZ = V_SZ + LG_SZ;
constexpr long long W2_B = (long long)R * L * H * L;     // per-b W2 floats
constexpr long long LG_B = (long long)R * L * L * L;     // per-b alpha floats

constexpr int SM_160_128 = (2 * 32 * 164 + 2 * 32 * 128) * 4;  // 74752
constexpr int SM_128_160 = (2 * 32 * 132 + 2 * 32 * 160) * 4;  // 74752
// <80,160> with softmax red buffer [80][20] appended
constexpr int SM_80_160S = (2 * 32 * 84 + 2 * 32 * 160 + 80 * 20) * 4;  // 68864
}

// ------------------------- static device scratch ----------------------------
__device__ float g_hidden[BATCH * L * 4 * H];    // [b*L+l][512]
__device__ float g_scoring[BATCH * L * 2 * H];   // [b*L+l][256]
__device__ float g_inPT[BATCH * HP * L];         // [b][j][z], row j=128 -> 1
__device__ float g_xtailPT[BATCH * HP * L];      // [b][m][y], row m=128 -> 1
__device__ float g_U[(long long)BATCH * R * L * NKJ];   // [(b*R+r)*L+y][k*129+j]
__device__ float g_G[(long long)BATCH * L * NKJ];       // [b][x][q*129+m]
__device__ float g_Gt2[(long long)BATCH * L * H * L];   // [b][x*128+q][y]
__device__ float g_Gt3[(long long)BATCH * L * L * H];   // [b][y][x*128+q]
__device__ float g_HRW[BATCH * L * H];                  // [b][z][q]
__device__ float g_arena[ARENA_SZ];

DINLINE float leaky(float v) { return v >= 0.f ? v : 0.1f * v; }

// ---- packed dual-FMA helpers (FFMA2 via PTX f32x2; sm_100+) ----------------
DINLINE u64 pack2(float x, float y) {
  u64 r;
  asm("mov.b64 %0, {%1, %2};" : "=l"(r) : "f"(x), "f"(y));
  return r;
}
DINLINE void unpack2(u64 v, float& x, float& y) {
  asm("mov.b64 {%0, %1}, %2;" : "=f"(x), "=f"(y) : "l"(v));
}
DINLINE void fma2(u64& acc, u64 a, u64 b) {
  asm("fma.rn.f32x2 %0, %1, %2, %0;" : "+l"(acc) : "l"(a), "l"(b));
}

// ---- cp.async helpers ------------------------------------------------------
DINLINE void cp4(uint32_t dst, const float* src) {
  asm volatile("cp.async.ca.shared.global [%0], [%1], 4;"
               :: "r"(dst), "l"(src));
}
DINLINE void cp16(uint32_t dst, const float* src) {
  asm volatile("cp.async.cg.shared.global [%0], [%1], 16;"
               :: "r"(dst), "l"(src));
}
#define CP_COMMIT() asm volatile("cp.async.commit_group;" ::: "memory")
#define CP_WAIT0()  asm volatile("cp.async.wait_group 0;" ::: "memory")

// ---- cp.async double-buffered GEMM, BK=32, 8x8 microtile, exact tiles -------
// Inner product uses fma.rn.f32x2 (2 fp32 FMA / issue); B operand pairs are
// loaded pre-packed from smem (contiguous), A pairs packed via mov.b64.
// Batched over blockIdx.z: bz = z / ZD, rz = z % ZD.
// ep: 0 none | 1 leaky(acc+bias[n]) | 2 acc+B[K][n] | 3 acc+A[m][K]
//     4 fused SP+score (BN==128; aux=Gt3; C=out base)
//     5 softmax over the full row before store (grid.x==1, BN==N;
//       extra smem red[BM][BN/8] appended after Bs)
template <int BM, int BN, int OCC>
__global__ void __launch_bounds__((BM / 8) * (BN / 8), OCC) gemm6(
    const float* __restrict__ A, const float* __restrict__ B,
    float* __restrict__ C, int M, int N, int K, int lda, int ldb, int ldc,
    long long sA, long long sA2, long long sB, long long sB2, long long sC,
    int ZD, int ep, const float* __restrict__ bias,
    const float* __restrict__ aux) {
  constexpr int NT = (BM / 8) * (BN / 8);
  constexpr int AST = BM + 4;
  constexpr int AR = (BM * 32 + NT - 1) / NT;
  constexpr int BR = (BN * 8 + NT - 1) / NT;
  extern __shared__ float smem[];
  float* As = smem;                 // [2][32][AST]
  float* Bs = smem + 2 * 32 * AST;  // [2][32][BN]
  const int z = blockIdx.z;
  const int bz = z / ZD, rz = z % ZD;
  A += bz * sA + rz * sA2;
  B += bz * sB + rz * sB2;
  C += (long long)z * sC;
  const int tid = threadIdx.x;
  const int tx = tid % (BN / 8), ty = tid / (BN / 8);
  const int m0 = blockIdx.y * BM, n0 = blockIdx.x * BN;

  const uint32_t sbA = (uint32_t)__cvta_generic_to_shared(As);
  const uint32_t sbB = (uint32_t)__cvta_generic_to_shared(Bs);

  auto prefetch = [&](int k0, int s) {
#pragma unroll
    for (int t = 0; t < AR; ++t) {
      int idx = tid + t * NT;
      if (idx < BM * 32) {
        int m = idx >> 5, k = idx & 31;
        cp4(sbA + (((s * 32 + k) * AST + m) << 2),
            A + (long long)(m0 + m) * lda + k0 + k);
      }
    }
#pragma unroll
    for (int t = 0; t < BR; ++t) {
      int idx = tid + t * NT;
      if (idx < BN * 8) {
        int k = idx / (BN / 4), n4 = idx % (BN / 4);
        cp16(sbB + (((s * 32 + k) * BN + n4 * 4) << 2),
             B + (long long)(k0 + k) * ldb + n0 + n4 * 4);
      }
    }
  };

  u64 acc2[8][4] = {};  // [i][p]: p0=(c0,c1) p1=(c2,c3) of lo-half; p2,p3 hi-half
  prefetch(0, 0);
  CP_COMMIT();
  int buf = 0;
  for (int k0 = 0; k0 < K; k0 += 32) {
    CP_WAIT0();
    __syncthreads();
    const bool next = (k0 + 32) < K;
    if (next) {
      prefetch(k0 + 32, buf ^ 1);
      CP_COMMIT();
    }
    const float* Ab = As + buf * 32 * AST;
    const float* Bb = Bs + buf * 32 * BN;
#pragma unroll 16
    for (int k = 0; k < 32; ++k) {
      float4 A0 = *(const float4*)(Ab + k * AST + ty * 4);
      float4 A1 = *(const float4*)(Ab + k * AST + BM / 2 + ty * 4);
      // B pairs are contiguous in smem: one 16B load = two packed operands
      ulonglong2 B0 = *(const ulonglong2*)(Bb + k * BN + tx * 4);
      ulonglong2 B1 = *(const ulonglong2*)(Bb + k * BN + BN / 2 + tx * 4);
      u64 a2[8];
      a2[0] = pack2(A0.x, A0.x); a2[1] = pack2(A0.y, A0.y);
      a2[2] = pack2(A0.z, A0.z); a2[3] = pack2(A0.w, A0.w);
      a2[4] = pack2(A1.x, A1.x); a2[5] = pack2(A1.y, A1.y);
      a2[6] = pack2(A1.z, A1.z); a2[7] = pack2(A1.w, A1.w);
#pragma unroll
      for (int i = 0; i < 8; ++i) {
        fma2(acc2[i][0], a2[i], B0.x);
        fma2(acc2[i][1], a2[i], B0.y);
        fma2(acc2[i][2], a2[i], B1.x);
        fma2(acc2[i][3], a2[i], B1.y);
      }
    }
    buf ^= 1;
  }
  // unpack into the canonical acc[][] layout; all epilogues unchanged below
  float acc[8][8];
#pragma unroll
  for (int i = 0; i < 8; ++i) {
    unpack2(acc2[i][0], acc[i][0], acc[i][1]);
    unpack2(acc2[i][1], acc[i][2], acc[i][3]);
    unpack2(acc2[i][2], acc[i][4], acc[i][5]);
    unpack2(acc2[i][3], acc[i][6], acc[i][7]);
  }
  // ---------------- epilogues (tile-exact; no M/N guards) ----------------
  if (ep == 4) {  // fused SP + score; BN==128, n0==0, m0==0
    const int r = rz / L, y = rz % L;
    float4 bb0 = *(const float4*)(bias + tx * 4);
    float4 bb1 = *(const float4*)(bias + BN / 2 + tx * 4);
    const float* gbase = aux + ((long long)(bz * L + y) * L) * H;
#pragma unroll
    for (int i = 0; i < 8; ++i) {
      int m = (i < 4 ? ty * 4 + i : BM / 2 + ty * 4 + (i - 4));
      float4 g0 = *(const float4*)(gbase + (long long)m * H + tx * 4);
      float4 g1 = *(const float4*)(gbase + (long long)m * H + BN / 2 + tx * 4);
      float s = leaky(acc[i][0] + bb0.x) * g0.x + leaky(acc[i][1] + bb0.y) * g0.y +
                leaky(acc[i][2] + bb0.z) * g0.z + leaky(acc[i][3] + bb0.w) * g0.w +
                leaky(acc[i][4] + bb1.x) * g1.x + leaky(acc[i][5] + bb1.y) * g1.y +
                leaky(acc[i][6] + bb1.z) * g1.z + leaky(acc[i][7] + bb1.w) * g1.w;
#pragma unroll
      for (int o = 8; o; o >>= 1) s += __shfl_xor_sync(0xffffffffu, s, o);
      if (tx == 0)
        C[((long long)((bz * R + r) * L + m)) * L + y] = s;
    }
    return;
  }
  if (ep == 5) {  // in-epilogue softmax over the full row (grid.x==1, BN==N)
    constexpr int NC = BN / 8;
    float* red = smem + 2 * 32 * AST + 2 * 32 * BN;  // [BM][NC]
    int mloc[8];
#pragma unroll
    for (int i = 0; i < 8; ++i)
      mloc[i] = (i < 4 ? ty * 4 + i : BM / 2 + ty * 4 + (i - 4));
    __syncthreads();
#pragma unroll
    for (int i = 0; i < 8; ++i) {
      float lm = acc[i][0];
#pragma unroll
      for (int j = 1; j < 8; ++j) lm = fmaxf(lm, acc[i][j]);
      red[mloc[i] * NC + tx] = lm;
    }
    __syncthreads();
    float mx[8];
#pragma unroll
    for (int i = 0; i < 8; ++i) {
      float m_ = red[mloc[i] * NC];
#pragma unroll
      for (int j = 1; j < NC; ++j) m_ = fmaxf(m_, red[mloc[i] * NC + j]);
      mx[i] = m_;
    }
    __syncthreads();
#pragma unroll
    for (int i = 0; i < 8; ++i) {
      float ls = 0.f;
#pragma unroll
      for (int j = 0; j < 8; ++j) {
        acc[i][j] = __expf(acc[i][j] - mx[i]);
        ls += acc[i][j];
      }
      red[mloc[i] * NC + tx] = ls;
    }
    __syncthreads();
#pragma unroll
    for (int i = 0; i < 8; ++i) {
      float s_ = 0.f;
#pragma unroll
      for (int j = 0; j < NC; ++j) s_ += red[mloc[i] * NC + j];
      float inv = 1.f / s_;
#pragma unroll
      for (int j = 0; j < 8; ++j) acc[i][j] *= inv;
    }
#pragma unroll
    for (int i = 0; i < 8; ++i) {
      int m = m0 + mloc[i];
#pragma unroll
      for (int jh = 0; jh < 2; ++jh) {
        int n = (jh ? BN / 2 : 0) + tx * 4;
        float4 v = make_float4(acc[i][jh * 4 + 0], acc[i][jh * 4 + 1],
                               acc[i][jh * 4 + 2], acc[i][jh * 4 + 3]);
        *(float4*)(C + (long long)m * ldc + n) = v;
      }
    }
    return;
  }
  float4 br0 = make_float4(0.f, 0.f, 0.f, 0.f), br1 = br0;
  if (ep == 2) {
    const float* Brow = B + (long long)K * ldb;
    br0 = *(const float4*)(Brow + n0 + tx * 4);
    br1 = *(const float4*)(Brow + n0 + BN / 2 + tx * 4);
  }
#pragma unroll
  for (int i = 0; i < 8; ++i) {
    int m = m0 + (i < 4 ? ty * 4 + i : BM / 2 + ty * 4 + (i - 4));
    float ra = (ep == 3) ? A[(long long)m * lda + K] : 0.f;
#pragma unroll
    for (int jh = 0; jh < 2; ++jh) {
      int n = n0 + (jh ? BN / 2 : 0) + tx * 4;
      float4 v = make_float4(acc[i][jh * 4 + 0], acc[i][jh * 4 + 1],
                             acc[i][jh * 4 + 2], acc[i][jh * 4 + 3]);
      if (ep == 1) {
        v.x = leaky(v.x + bias[n + 0]);
        v.y = leaky(v.y + bias[n + 1]);
        v.z = leaky(v.z + bias[n + 2]);
        v.w = leaky(v.w + bias[n + 3]);
      } else if (ep == 2) {
        float4 br = jh ? br1 : br0;
        v.x += br.x; v.y += br.y; v.z += br.z; v.w += br.w;
      } else if (ep == 3) {
        v.x += ra; v.y += ra; v.z += ra; v.w += ra;
      }
      *(float4*)(C + (long long)m * ldc + n) = v;
    }
  }
}

// ---------------- prep: inPT / xtailPT transposes ---------------------------
__global__ void k_prep2() {
  int t = blockIdx.x * blockDim.x + threadIdx.x;
  const int NPAD = BATCH * HP * L;  // 41280
  if (t < NPAD) {
    int b = t / (HP * L), rem = t % (HP * L);
    int j = rem / L, zz = rem % L;
    g_inPT[t] = (j < H)
        ? g_hidden[(long long)(b * L + zz) * (4 * H) + 3 * H + j] : 1.f;
    return;
  }
  t -= NPAD;
  if (t < NPAD) {
    int b = t / (HP * L), rem = t % (HP * L);
    int m = rem / L, y = rem % L;
    g_xtailPT[t] = (m < H)
        ? g_scoring[(long long)(b * L + y) * (2 * H) + H + m] : 1.f;
  }
}

// ---------------- Gt2[b][xq][y] -> Gt3[b][y][xq] (tiled transpose) ----------
__global__ void k_transpose(const float* __restrict__ in,
                            float* __restrict__ outp) {
  __shared__ float t[32][33];
  int b = blockIdx.z;
  int xq0 = blockIdx.x * 32, y0 = blockIdx.y * 32;
  const float* ip = in + (long long)b * (L * H) * L;
  float* op = outp + (long long)b * L * (L * H);
  int tx = threadIdx.x, ty0 = threadIdx.y;  // 32 x 8
  for (int i = ty0; i < 32; i += 8)
    t[i][tx] = ip[(long long)(xq0 + i) * L + (y0 + tx)];
  __syncthreads();
  for (int i = ty0; i < 32; i += 8)
    op[(long long)(y0 + i) * (L * H) + (xq0 + tx)] = t[tx][i];
}

// ------------------------------- launch --------------------------------------
static const float* pick_by_size(void* const* d_in, const int* in_sizes,
                                 int n_in, int want, int fallback_idx) {
  for (int i = 0; i < n_in; ++i)
    if (in_sizes[i] == want) return (const float*)d_in[i];
  return (const float*)d_in[fallback_idx];
}

extern "C" void kernel_launch(void* const* d_in, const int* in_sizes, int n_in,
                              void* d_out, int out_size) {
  (void)out_size;
  const float* x      = pick_by_size(d_in, in_sizes, n_in, BATCH * L * D, 0);
  const float* Wspan  = pick_by_size(d_in, in_sizes, n_in, D * 4 * H, 1);
  const float* bspan  = pick_by_size(d_in, in_sizes, n_in, 4 * H, 2);
  const float* Wscore = pick_by_size(d_in, in_sizes, n_in, D * 2 * H, 3);
  const float* bscore = pick_by_size(d_in, in_sizes, n_in, 2 * H, 4);
  const float* Wtri   = pick_by_size(d_in, in_sizes, n_in, R * HP * H * HP, 5);
  const float* Wmlp   = pick_by_size(d_in, in_sizes, n_in, H * H, 6);
  const float* bmlp   = pick_by_size(d_in, in_sizes, n_in, H, 7);
  const float* Wfin   = pick_by_size(d_in, in_sizes, n_in, HP * H * HP, 8);
  float* out = (float*)d_out;

  float* d_hidden;  cudaGetSymbolAddress((void**)&d_hidden, g_hidden);
  float* d_scoring; cudaGetSymbolAddress((void**)&d_scoring, g_scoring);
  float* d_inPT;    cudaGetSymbolAddress((void**)&d_inPT, g_inPT);
  float* d_xtailPT; cudaGetSymbolAddress((void**)&d_xtailPT, g_xtailPT);
  float* d_U;       cudaGetSymbolAddress((void**)&d_U, g_U);
  float* d_G;       cudaGetSymbolAddress((void**)&d_G, g_G);
  float* d_Gt2;     cudaGetSymbolAddress((void**)&d_Gt2, g_Gt2);
  float* d_Gt3;     cudaGetSymbolAddress((void**)&d_Gt3, g_Gt3);
  float* d_HRW;     cudaGetSymbolAddress((void**)&d_HRW, g_HRW);
  float* d_arena;   cudaGetSymbolAddress((void**)&d_arena, g_arena);
  float* d_W2 = d_arena + OFF_V;   // [b][(r,y)][k][z]
  float* d_LG = d_arena + OFF_LG;  // alpha [b][(r,y)][x][z]

  cudaFuncSetAttribute(gemm6<160, 128, 2>,
                       cudaFuncAttributeMaxDynamicSharedMemorySize, SM_160_128);
  cudaFuncSetAttribute(gemm6<128, 160, 2>,
                       cudaFuncAttributeMaxDynamicSharedMemorySize, SM_128_160);
  cudaFuncSetAttribute(gemm6<80, 160, 3>,
                       cudaFuncAttributeMaxDynamicSharedMemorySize, SM_80_160S);

  // 1) hidden = leaky(x @ Wspan + bspan)   [320,512], K=768
  gemm6<160, 128, 2><<<dim3(4, 2, 1), 320, SM_160_128>>>(
      x, Wspan, d_hidden, 320, 512, 768, 768, 512, 512,
      0, 0, 0, 0, 0, 1, 1, bspan, nullptr);
  // 2) scoring = leaky(x @ Wscore + bscore) [320,256], K=768
  gemm6<160, 128, 2><<<dim3(2, 2, 1), 320, SM_160_128>>>(
      x, Wscore, d_scoring, 320, 256, 768, 768, 256, 256,
      0, 0, 0, 0, 0, 1, 1, bscore, nullptr);
  // 3) transposes for inPT / xtailPT
  k_prep2<<<(2 * BATCH * HP * L + 255) / 256, 256>>>();
  // 4) U[(b,r)] = h_tail[b] @ Wtri[r][0:128] + Wtri[r][128]; z=(b,r), ZD=R
  gemm6<160, 128, 2><<<dim3(129, 1, BATCH * R), 320, SM_160_128>>>(
      d_hidden + 2 * H, Wtri, d_U, L, NKJ, H, 4 * H, NKJ, NKJ,
      (long long)L * (4 * H), 0, 0, WTRI_R, (long long)L * NKJ,
      R, 2, nullptr, nullptr);
  // 5) G[b] = x_head[b] @ Wfin[0:128] + Wfin[128]; z=b
  gemm6<160, 128, 2><<<dim3(129, 1, BATCH), 320, SM_160_128>>>(
      d_scoring, Wfin, d_G, L, NKJ, H, 2 * H, NKJ, NKJ,
      (long long)L * (2 * H), 0, 0, 0, (long long)L * NKJ,
      1, 2, nullptr, nullptr);
  // 6) Gt2[b] = G[b][:, 0:128] @ xtailPT[b][0:128] + G[..][128]; z=b
  gemm6<128, 160, 2><<<dim3(1, 160, BATCH), 320, SM_128_160>>>(
      d_G, d_xtailPT, d_Gt2, L * H, L, H, HP, L, L,
      (long long)L * NKJ, 0, (long long)HP * L, 0, (long long)(L * H) * L,
      1, 3, nullptr, nullptr);
  // 6b) Gt3[b][y][xq] = transpose(Gt2)
  k_transpose<<<dim3(640, 5, 2), dim3(32, 8)>>>(d_Gt2, d_Gt3);
  // 7) W2[z] = U[z][:, 0:128] @ inPT[b][0:128] + U[z][:, 128]; z=(b,(r,y))
  gemm6<128, 160, 2><<<dim3(1, 1, BATCH * R * L), 320, SM_128_160>>>(
      d_U, d_inPT, d_W2, H, L, H, HP, L, L,
      (long long)R * L * NKJ, NKJ, (long long)HP * L, 0, (long long)H * L,
      R * L, 3, nullptr, nullptr);
  // 8+9) alpha[z] = softmax(h_head[b] @ W2[z]) — softmax fused in epilogue
  gemm6<80, 160, 3><<<dim3(1, 2, BATCH * R * L), 200, SM_80_160S>>>(
      d_hidden + H, d_W2, d_LG, L, L, H, 4 * H, L, L,
      (long long)L * (4 * H), 0, W2_B, (long long)H * L, (long long)L * L,
      R * L, 5, nullptr, nullptr);
  // 10) HRW[b] = h_in_repr[b] [160,128] @ Wmlp [128,128]; z=b
  gemm6<160, 128, 2><<<dim3(1, 1, BATCH), 320, SM_160_128>>>(
      d_hidden, Wmlp, d_HRW, L, H, H, 4 * H, H, H,
      (long long)L * (4 * H), 0, 0, 0, (long long)L * H,
      1, 0, nullptr, nullptr);
  // 11) fused: SP = leaky(alpha @ HRW + bmlp); out = sum_q SP*Gt3 (ep=4)
  gemm6<160, 128, 2><<<dim3(1, 1, BATCH * R * L), 320, SM_160_128>>>(
      d_LG, d_HRW, out, L, H, L, L, H, 0,
      LG_B, (long long)L * L, (long long)L * H, 0, 0,
      R * L, 4, bmlp, d_Gt3);
}